// round 11
// baseline (speedup 1.0000x reference)
#include <cuda_runtime.h>
#include <cuda_bf16.h>
#include <cstdint>
#include <math.h>

// Problem constants (fixed by the dataset)
#define DIMK   2048              // feature dim D
#define PBANK  2048              // pseudo-ID classes per camera
#define CCAM   8                 // cameras
#define NTOT   (CCAM * PBANK)    // 16384 memory rows
#define KSEL   50                // hard-negative K
#define TEMP   0.07f
#define BMAX   256               // batch size
#define CAPN   4096              // candidate-list capacity (fallback if exceeded)

// ---------------- device scratch (no cudaMalloc allowed) ----------------
__device__ __align__(16) __nv_bfloat16 g_xb[BMAX * DIMK];    // normalized x, bf16 (1 MB)
__device__ __align__(16) float g_logits[BMAX * NTOT];        // 16 MB
__device__ float g_ce[BMAX];
__device__ float g_lk[BMAX];
__device__ unsigned g_done = 0;                              // last-block counter

// ---------------- small utils ----------------
__device__ __forceinline__ float warp_sum(float v) {
#pragma unroll
    for (int o = 16; o; o >>= 1) v += __shfl_xor_sync(0xffffffffu, v, o);
    return v;
}
__device__ __forceinline__ float warp_max(float v) {
#pragma unroll
    for (int o = 16; o; o >>= 1) v = fmaxf(v, __shfl_xor_sync(0xffffffffu, v, o));
    return v;
}
__device__ __forceinline__ float block_sum(float v, float* scr) {
    v = warp_sum(v);
    __syncthreads();
    if ((threadIdx.x & 31) == 0) scr[threadIdx.x >> 5] = v;
    __syncthreads();
    float r = scr[0];
#pragma unroll
    for (int w = 1; w < 8; w++) r += scr[w];
    return r;
}
__device__ __forceinline__ float block_max(float v, float* scr) {
    v = warp_max(v);
    __syncthreads();
    if ((threadIdx.x & 31) == 0) scr[threadIdx.x >> 5] = v;
    __syncthreads();
    float r = scr[0];
#pragma unroll
    for (int w = 1; w < 8; w++) r = fmaxf(r, scr[w]);
    return r;
}
__device__ __forceinline__ unsigned fkey(float f) {
    unsigned u = __float_as_uint(f);
    return (u & 0x80000000u) ? ~u : (u | 0x80000000u);
}
__device__ __forceinline__ float funkey(unsigned k) {
    unsigned u = (k & 0x80000000u) ? (k ^ 0x80000000u) : ~k;
    return __uint_as_float(u);
}
// aggregated shared histogram add over active-lane mask `bal`
__device__ __forceinline__ void agg_hist_add(unsigned* hist, unsigned bin, unsigned bal, int lane) {
    unsigned mm = __match_any_sync(bal, bin);
    if (lane == __ffs(mm) - 1) atomicAdd(&hist[bin], (unsigned)__popc(mm));
}

// ---------------- cp.async helpers ----------------
__device__ __forceinline__ void cp_async16(uint32_t smem_addr, const void* gptr) {
    asm volatile("cp.async.cg.shared.global [%0], [%1], 16;\n"
                 :: "r"(smem_addr), "l"(gptr));
}
__device__ __forceinline__ void cp_commit() { asm volatile("cp.async.commit_group;\n" ::); }
__device__ __forceinline__ void cp_wait1()  { asm volatile("cp.async.wait_group 1;\n" ::); }
__device__ __forceinline__ void cp_wait0()  { asm volatile("cp.async.wait_group 0;\n" ::); }

__device__ __forceinline__ void mma_bf16(float c[4], const uint32_t a[4], const uint32_t b[2]) {
    asm volatile(
        "mma.sync.aligned.m16n8k16.row.col.f32.bf16.bf16.f32 "
        "{%0,%1,%2,%3}, {%4,%5,%6,%7}, {%8,%9}, {%0,%1,%2,%3};\n"
        : "+f"(c[0]), "+f"(c[1]), "+f"(c[2]), "+f"(c[3])
        : "r"(a[0]), "r"(a[1]), "r"(a[2]), "r"(a[3]), "r"(b[0]), "r"(b[1]));
}
__device__ __forceinline__ uint32_t cvt_bf16x2(float lo, float hi) {
    __nv_bfloat162 p = __floats2bfloat162_rn(lo, hi);
    return *(unsigned*)&p;
}

// ---------------- kernel 1: row L2-normalize -> bf16 ----------------
__global__ __launch_bounds__(256) void prep_kernel(const float* __restrict__ in) {
    __shared__ float scr[8];
    const int b = blockIdx.x;
    const float4* row = (const float4*)(in + (size_t)b * DIMK);
    float s = 0.f;
    for (int i = threadIdx.x; i < DIMK / 4; i += 256) {
        float4 a = row[i];
        s += a.x * a.x + a.y * a.y + a.z * a.z + a.w * a.w;
    }
    s = block_sum(s, scr);
    const float inv = rsqrtf(s);
    for (int i = threadIdx.x; i < DIMK / 4; i += 256) {
        float4 a = row[i];
        uint2 o;
        o.x = cvt_bf16x2(a.x * inv, a.y * inv);
        o.y = cvt_bf16x2(a.z * inv, a.w * inv);
        *(uint2*)(g_xb + (size_t)b * DIMK + (size_t)i * 4) = o;
    }
}

// ---------------- kernel 2: bf16 GEMM, B streamed as fp32 + in-register convert ----------------
#define AROW_U  20
#define BROW_F  40
#define A_STAGE_U (128 * AROW_U)
#define B_STAGE_F (128 * BROW_F)
#define STAGE_U   (A_STAGE_U + B_STAGE_F)
#define NKSTEP  (DIMK / 32)
#define GSMEM   (3 * STAGE_U * 4)

__device__ __forceinline__ void gemm_load_stage(uint32_t smb, int stage, int bm, int bn,
                                                int k0, const float* __restrict__ Bv,
                                                int tid) {
    const uint32_t a_base = smb + stage * (STAGE_U * 4);
    const uint32_t b_base = a_base + A_STAGE_U * 4;
#pragma unroll
    for (int it = 0; it < 2; it++) {
        int idx = tid + it * 256;
        int r = idx >> 2, seg = idx & 3;
        const __nv_bfloat16* gp = g_xb + (size_t)(bm * 128 + r) * DIMK + k0 + seg * 8;
        cp_async16(a_base + (uint32_t)(r * AROW_U + seg * 4) * 4u, gp);
    }
#pragma unroll
    for (int it = 0; it < 4; it++) {
        int idx = tid + it * 256;
        int r = idx >> 3, seg = idx & 7;
        const float* gp = Bv + (size_t)(bn * 128 + r) * DIMK + k0 + seg * 4;
        cp_async16(b_base + (uint32_t)(r * BROW_F + seg * 4) * 4u, gp);
    }
    cp_commit();
}

__global__ __launch_bounds__(256) void gemm_bf16(const float* __restrict__ Bv, int Brows) {
    extern __shared__ uint32_t sm[];
    const int bm = blockIdx.x, bn = blockIdx.y;
    const int tid = threadIdx.x, lane = tid & 31, warp = tid >> 5;
    const int wm = warp >> 2, wn = warp & 3;
    const int g = lane >> 2, tg = lane & 3;

    uint32_t smb;
    asm("{ .reg .u64 t; cvta.to.shared.u64 t, %1; cvt.u32.u64 %0, t; }" : "=r"(smb) : "l"(sm));

    float acc[4][4][4];
#pragma unroll
    for (int i = 0; i < 4; i++)
#pragma unroll
        for (int j = 0; j < 4; j++)
#pragma unroll
            for (int r = 0; r < 4; r++) acc[i][j][r] = 0.f;

    gemm_load_stage(smb, 0, bm, bn, 0, Bv, tid);
    gemm_load_stage(smb, 1, bm, bn, 32, Bv, tid);

    for (int kt = 0; kt < NKSTEP; kt++) {
        if (kt >= NKSTEP - 2) cp_wait0(); else cp_wait1();
        __syncthreads();

        const uint32_t* As = sm + (kt % 3) * STAGE_U;
        const float*    Bs = (const float*)(As + A_STAGE_U);

#pragma unroll
        for (int ks = 0; ks < 2; ks++) {
            const int kbA = ks * 8;
            const int kbB = ks * 16;
            uint32_t af[4][4];
            uint32_t bf[4][2];
#pragma unroll
            for (int i = 0; i < 4; i++) {
                int r0 = wm * 64 + i * 16 + g;
                af[i][0] = As[r0 * AROW_U + kbA + tg];
                af[i][1] = As[(r0 + 8) * AROW_U + kbA + tg];
                af[i][2] = As[r0 * AROW_U + kbA + tg + 4];
                af[i][3] = As[(r0 + 8) * AROW_U + kbA + tg + 4];
            }
#pragma unroll
            for (int j = 0; j < 4; j++) {
                int n0 = wn * 32 + j * 8 + g;
                float2 p0 = *(const float2*)(Bs + n0 * BROW_F + kbB + 2 * tg);
                float2 p1 = *(const float2*)(Bs + n0 * BROW_F + kbB + 2 * tg + 8);
                bf[j][0] = cvt_bf16x2(p0.x, p0.y);
                bf[j][1] = cvt_bf16x2(p1.x, p1.y);
            }
#pragma unroll
            for (int i = 0; i < 4; i++)
#pragma unroll
                for (int j = 0; j < 4; j++) mma_bf16(acc[i][j], af[i], bf[j]);
        }

        if (kt + 2 < NKSTEP)
            gemm_load_stage(smb, (kt + 2) % 3, bm, bn, (kt + 2) * 32, Bv, tid);
    }

#pragma unroll
    for (int i = 0; i < 4; i++) {
#pragma unroll
        for (int j = 0; j < 4; j++) {
            int row = bm * 128 + wm * 64 + i * 16 + g;
            int col = bn * 128 + wn * 32 + j * 8 + 2 * tg;
            if (row < Brows)
                *(float2*)(g_logits + (size_t)row * NTOT + col) =
                    make_float2(acc[i][j][0], acc[i][j][1]);
            if (row + 8 < Brows)
                *(float2*)(g_logits + (size_t)(row + 8) * NTOT + col) =
                    make_float2(acc[i][j][2], acc[i][j][3]);
        }
    }
}

// ---------------- kernel 3: fused per-row losses + final reduce ----------------
__global__ __launch_bounds__(256) void rowloss_kernel(const int* __restrict__ labels,
                                                      const int* __restrict__ cams,
                                                      float* __restrict__ out) {
    extern __shared__ float srow[];        // NTOT floats (64 KB)
    __shared__ float scr[8];
    __shared__ float s_ori[CCAM];
    __shared__ unsigned hist[256];
    __shared__ unsigned sh_prefix;
    __shared__ int sh_need, sh_cum;
    __shared__ unsigned short cand[CAPN];
    __shared__ unsigned s_wcnt[9];
    __shared__ unsigned s_last;

    const int b = blockIdx.x, tid = threadIdx.x;
    const int lane = tid & 31, warpid = tid >> 5;
    const int cam = cams[b], label = labels[b];
    const float invT = 1.0f / TEMP;
    const float* row = g_logits + (size_t)b * NTOT;

    // ---- pass 1: load global -> SMEM, global max, top-byte histogram (unmasked) ----
    hist[tid] = 0u;
    __syncthreads();
    float lmax = -1e30f;
#pragma unroll 4
    for (int i = tid; i < NTOT; i += 256) {
        float v = row[i];
        srow[i] = v;
        lmax = fmaxf(lmax, v);
        agg_hist_add(hist, fkey(v) >> 24, 0xffffffffu, lane);
    }
    const float M = block_max(lmax, scr);   // unmasked max = valid stabilizer everywhere

    // ---- save positives, mask them, correct histogram ----
    if (tid < CCAM) {
        float ov = srow[tid * PBANK + label];
        s_ori[tid] = ov;
        srow[tid * PBANK + label] = -10000.0f;
        atomicSub(&hist[fkey(ov) >> 24], 1u);
        atomicAdd(&hist[fkey(-10000.0f) >> 24], 1u);
    }
    __syncthreads();

    // ---- select top-byte bin ----
    if (tid == 0) {
        int cum = 0, bsel = 0;
        for (int bb = 255; bb >= 0; --bb) {
            int h = (int)hist[bb];
            if (cum + h >= KSEL) { bsel = bb; break; }
            cum += h;
        }
        sh_cum = cum;
        sh_prefix = (unsigned)bsel << 24;
    }
    __syncthreads();
    const unsigned bin1 = sh_prefix >> 24;
    const int need1 = KSEL - sh_cum;
    unsigned prefix = sh_prefix;

    // ---- pass 2 (one SMEM scan): sum-above, intra-bank sum, candidate counts ----
    float sacc = 0.f, sintra = 0.f;
    int my_cnt = 0;
#pragma unroll 4
    for (int i = tid; i < NTOT; i += 256) {
        float v = srow[i];
        unsigned tb = fkey(v) >> 24;
        float e = expf((v - M) * invT);
        if (tb > bin1) sacc += e;
        else if (tb == bin1) my_cnt++;
        if ((i >> 11) == cam) sintra += e;
    }
    // deterministic block exclusive scan of my_cnt
    {
        int x = my_cnt;
#pragma unroll
        for (int o = 1; o < 32; o <<= 1) {
            int y = __shfl_up_sync(0xffffffffu, x, o);
            if (lane >= o) x += y;
        }
        if (lane == 31) s_wcnt[warpid] = (unsigned)x;
        __syncthreads();
        if (tid == 0) {
            unsigned run = 0;
#pragma unroll
            for (int w = 0; w < 8; w++) { unsigned t = s_wcnt[w]; s_wcnt[w] = run; run += t; }
            s_wcnt[8] = run;
        }
        __syncthreads();
        my_cnt = (int)s_wcnt[warpid] + (x - my_cnt);   // exclusive offset for this thread
    }
    const int total = (int)s_wcnt[8];
    const bool fb = (total > CAPN);                    // fallback: full scans

    // ---- compaction + byte-2 histogram (histogram valid even on overflow) ----
    hist[tid] = 0u;
    __syncthreads();
    {
        int pos = my_cnt;
#pragma unroll 4
        for (int i = tid; i < NTOT; i += 256) {
            unsigned key = fkey(srow[i]);
            bool ok = ((key >> 24) == bin1);
            unsigned bal = __ballot_sync(0xffffffffu, ok);
            if (ok) {
                if (pos < CAPN) cand[pos] = (unsigned short)i;
                pos++;
                agg_hist_add(hist, (key >> 16) & 0xFFu, bal, lane);
            }
        }
    }
    __syncthreads();

    // ---- select byte 2 ----
    if (tid == 0) {
        int cum = 0, bsel = 0, need = need1;
        for (int bb = 255; bb >= 0; --bb) {
            int h = (int)hist[bb];
            if (cum + h >= need) { bsel = bb; break; }
            cum += h;
        }
        sh_need = need1 - cum;
        sh_prefix = prefix | ((unsigned)bsel << 16);
    }
    __syncthreads();
    prefix = sh_prefix;
    int need = sh_need;
    __syncthreads();

    // ---- passes 3 & 4 over candidates (or full fallback) ----
#pragma unroll
    for (int p = 0; p < 2; p++) {
        const int shift = 8 - 8 * p;
        hist[tid] = 0u;
        __syncthreads();
        if (!fb) {
            for (int j0 = 0; j0 < total; j0 += 256) {
                int j = j0 + tid;
                bool in = (j < total);
                unsigned key = 0;
                if (in) key = fkey(srow[cand[j]]);
                bool ok = in && ((key >> (shift + 8)) == (prefix >> (shift + 8)));
                unsigned bal = __ballot_sync(0xffffffffu, ok);
                if (ok) agg_hist_add(hist, (key >> shift) & 0xFFu, bal, lane);
            }
        } else {
            for (int i = tid; i < NTOT; i += 256) {
                unsigned key = fkey(srow[i]);
                bool ok = ((key >> (shift + 8)) == (prefix >> (shift + 8)));
                unsigned bal = __ballot_sync(0xffffffffu, ok);
                if (ok) agg_hist_add(hist, (key >> shift) & 0xFFu, bal, lane);
            }
        }
        __syncthreads();
        if (tid == 0) {
            int cum = 0, bsel = 0;
            for (int bb = 255; bb >= 0; --bb) {
                int h = (int)hist[bb];
                if (cum + h >= need) { bsel = bb; break; }
                cum += h;
            }
            sh_need = need - cum;
            sh_prefix = prefix | ((unsigned)bsel << shift);
        }
        __syncthreads();
        prefix = sh_prefix;
        need = sh_need;
        __syncthreads();
    }
    const float tval = funkey(prefix);

    // ---- final partial sum over candidates strictly above threshold ----
    float sacc2 = 0.f;
    if (!fb) {
        for (int j0 = 0; j0 < total; j0 += 256) {
            int j = j0 + tid;
            if (j < total) {
                float v = srow[cand[j]];
                if (fkey(v) > prefix) sacc2 += expf((v - M) * invT);
            }
        }
    } else {
        for (int i = tid; i < NTOT; i += 256) {
            float v = srow[i];
            unsigned key = fkey(v);
            if ((key >> 24) == bin1 && key > prefix) sacc2 += expf((v - M) * invT);
        }
    }

    const float ssum_above = block_sum(sacc, scr);
    const float ssum_cand  = block_sum(sacc2, scr);
    const float ssum_intra = block_sum(sintra, scr);

    if (tid == 0) {
        // intra CE (global-max stabilized; add back masked positive's exp term)
        float se = ssum_intra + expf((s_ori[cam] - M) * invT);
        g_ce[b] = M * invT + logf(se) - s_ori[cam] * invT;
        // inter loss
        float ssel = ssum_above + ssum_cand + (float)need * expf((tval - M) * invT);
        float sori = 0.f, osum = 0.f;
#pragma unroll
        for (int c = 0; c < CCAM; c++) {
            sori += expf((s_ori[c] - M) * invT);
            osum += s_ori[c];
        }
        float lse = M * invT + logf(ssel + sori);
        g_lk[b] = lse - osum * invT * (1.0f / (float)CCAM);
    }

    // ---- last-block final reduction (replaces final_kernel) ----
    __threadfence();
    __syncthreads();
    if (tid == 0) s_last = (atomicAdd(&g_done, 1u) == gridDim.x - 1) ? 1u : 0u;
    __syncthreads();
    if (s_last) {
        __threadfence();
        const int B = (int)gridDim.x;
        const int w = warpid;            // camera id (8 warps = 8 cams)
        float se = 0.f, sl = 0.f, cn = 0.f;
        for (int i = lane; i < B; i += 32) {
            if (cams[i] == w) { se += g_ce[i]; sl += g_lk[i]; cn += 1.f; }
        }
        se = warp_sum(se);
        sl = warp_sum(sl);
        cn = warp_sum(cn);
        if (lane == 0) {
            s_ori[w]  = (cn > 0.f) ? se / cn : 0.f;   // reuse s_ori as intra means
            scr[w]    = (cn > 0.f) ? sl / cn : 0.f;   // reuse scr as inter means
        }
        __syncthreads();
        if (tid == 0) {
            float a = 0.f, bsum = 0.f;
#pragma unroll
            for (int k = 0; k < CCAM; k++) { a += s_ori[k]; bsum += scr[k]; }
            out[0] = a;           // loss_intra
            out[1] = 0.5f * bsum; // loss_inter (LOSS_WEIGHT = 0.5)
            g_done = 0;           // reset for next graph replay
        }
    }
}

// ---------------- launch ----------------
extern "C" void kernel_launch(void* const* d_in, const int* in_sizes, int n_in,
                              void* d_out, int out_size) {
    const float* inputs = (const float*)d_in[0];
    const int*   labels = (const int*)d_in[1];
    const int*   cams   = (const int*)d_in[2];
    const float* tempV  = (const float*)d_in[3];
    const int B = in_sizes[1];  // labels element count

    prep_kernel<<<B, 256>>>(inputs);

    cudaFuncSetAttribute(gemm_bf16, cudaFuncAttributeMaxDynamicSharedMemorySize, GSMEM);
    dim3 grid((B + 127) / 128, NTOT / 128);   // bm fastest -> B-tile shared via L2
    gemm_bf16<<<grid, 256, GSMEM>>>(tempV, B);

    cudaFuncSetAttribute(rowloss_kernel, cudaFuncAttributeMaxDynamicSharedMemorySize,
                         NTOT * (int)sizeof(float));
    rowloss_kernel<<<B, 256, NTOT * sizeof(float)>>>(labels, cams, (float*)d_out);
}

// round 14
// speedup vs baseline: 1.0606x; 1.0606x over previous
#include <cuda_runtime.h>
#include <cuda_bf16.h>
#include <cstdint>
#include <math.h>

// Problem constants (fixed by the dataset)
#define DIMK   2048              // feature dim D
#define PBANK  2048              // pseudo-ID classes per camera
#define CCAM   8                 // cameras
#define NTOT   (CCAM * PBANK)    // 16384 memory rows
#define KSEL   50                // hard-negative K
#define TEMP   0.07f
#define BMAX   256               // batch size

// ---------------- device scratch (no cudaMalloc allowed) ----------------
__device__ __align__(16) __nv_bfloat16 g_xb[BMAX * DIMK];    // normalized x, bf16 (1 MB)
__device__ __align__(16) float g_logits[BMAX * NTOT];        // 16 MB
__device__ float g_ce[BMAX];
__device__ float g_lk[BMAX];

// ---------------- small utils ----------------
__device__ __forceinline__ float warp_sum(float v) {
#pragma unroll
    for (int o = 16; o; o >>= 1) v += __shfl_xor_sync(0xffffffffu, v, o);
    return v;
}
__device__ __forceinline__ float warp_max(float v) {
#pragma unroll
    for (int o = 16; o; o >>= 1) v = fmaxf(v, __shfl_xor_sync(0xffffffffu, v, o));
    return v;
}
__device__ __forceinline__ float block_sum(float v, float* scr) {
    v = warp_sum(v);
    __syncthreads();
    if ((threadIdx.x & 31) == 0) scr[threadIdx.x >> 5] = v;
    __syncthreads();
    float r = scr[0];
#pragma unroll
    for (int w = 1; w < 8; w++) r += scr[w];
    return r;
}
__device__ __forceinline__ float block_max(float v, float* scr) {
    v = warp_max(v);
    __syncthreads();
    if ((threadIdx.x & 31) == 0) scr[threadIdx.x >> 5] = v;
    __syncthreads();
    float r = scr[0];
#pragma unroll
    for (int w = 1; w < 8; w++) r = fmaxf(r, scr[w]);
    return r;
}
__device__ __forceinline__ unsigned fkey(float f) {
    unsigned u = __float_as_uint(f);
    return (u & 0x80000000u) ? ~u : (u | 0x80000000u);
}
__device__ __forceinline__ float funkey(unsigned k) {
    unsigned u = (k & 0x80000000u) ? (k ^ 0x80000000u) : ~k;
    return __uint_as_float(u);
}

// ---------------- cp.async / mma helpers ----------------
__device__ __forceinline__ void cp_async16(uint32_t smem_addr, const void* gptr) {
    asm volatile("cp.async.cg.shared.global [%0], [%1], 16;\n"
                 :: "r"(smem_addr), "l"(gptr));
}
__device__ __forceinline__ void cp_commit() { asm volatile("cp.async.commit_group;\n" ::); }
__device__ __forceinline__ void cp_wait1()  { asm volatile("cp.async.wait_group 1;\n" ::); }
__device__ __forceinline__ void cp_wait0()  { asm volatile("cp.async.wait_group 0;\n" ::); }

__device__ __forceinline__ void mma_bf16(float c[4], const uint32_t a[4], const uint32_t b[2]) {
    asm volatile(
        "mma.sync.aligned.m16n8k16.row.col.f32.bf16.bf16.f32 "
        "{%0,%1,%2,%3}, {%4,%5,%6,%7}, {%8,%9}, {%0,%1,%2,%3};\n"
        : "+f"(c[0]), "+f"(c[1]), "+f"(c[2]), "+f"(c[3])
        : "r"(a[0]), "r"(a[1]), "r"(a[2]), "r"(a[3]), "r"(b[0]), "r"(b[1]));
}
__device__ __forceinline__ void ldmatrix_x4(uint32_t r[4], uint32_t addr) {
    asm volatile("ldmatrix.sync.aligned.m8n8.x4.shared.b16 {%0,%1,%2,%3}, [%4];"
                 : "=r"(r[0]), "=r"(r[1]), "=r"(r[2]), "=r"(r[3]) : "r"(addr));
}
__device__ __forceinline__ uint32_t cvt_bf16x2(float lo, float hi) {
    __nv_bfloat162 p = __floats2bfloat162_rn(lo, hi);
    return *(unsigned*)&p;
}

// ---------------- kernel 1: row L2-normalize -> bf16 ----------------
__global__ __launch_bounds__(256) void prep_kernel(const float* __restrict__ in) {
    __shared__ float scr[8];
    const int b = blockIdx.x;
    const float4* row = (const float4*)(in + (size_t)b * DIMK);
    float s = 0.f;
    for (int i = threadIdx.x; i < DIMK / 4; i += 256) {
        float4 a = row[i];
        s += a.x * a.x + a.y * a.y + a.z * a.z + a.w * a.w;
    }
    s = block_sum(s, scr);
    const float inv = rsqrtf(s);
    for (int i = threadIdx.x; i < DIMK / 4; i += 256) {
        float4 a = row[i];
        uint2 o;
        o.x = cvt_bf16x2(a.x * inv, a.y * inv);
        o.y = cvt_bf16x2(a.z * inv, a.w * inv);
        *(uint2*)(g_xb + (size_t)b * DIMK + (size_t)i * 4) = o;
    }
}

// ---------------- kernel 2: bf16 GEMM, occupancy 2, ldmatrix A-frags ----------------
// Block tile 128(M) x 128(N), K-step 32, 3-stage cp.async pipeline.
// A (bf16): row = 16 data uints + 4 pad = 20 uints (80 B; ldmatrix phases conflict-free).
// B (fp32): row = 32 data floats + 8 pad = 40 floats (LDS.64 frag loads conflict-free).
#define AROW_U  20
#define BROW_F  40
#define A_STAGE_U (128 * AROW_U)
#define B_STAGE_F (128 * BROW_F)
#define STAGE_U   (A_STAGE_U + B_STAGE_F)
#define NKSTEP  (DIMK / 32)
#define GSMEM   (3 * STAGE_U * 4)

__device__ __forceinline__ void gemm_load_stage(uint32_t smb, int stage, int bm, int bn,
                                                int k0, const float* __restrict__ Bv,
                                                int tid) {
    const uint32_t a_base = smb + stage * (STAGE_U * 4);
    const uint32_t b_base = a_base + A_STAGE_U * 4;
#pragma unroll
    for (int it = 0; it < 2; it++) {
        int idx = tid + it * 256;
        int r = idx >> 2, seg = idx & 3;
        const __nv_bfloat16* gp = g_xb + (size_t)(bm * 128 + r) * DIMK + k0 + seg * 8;
        cp_async16(a_base + (uint32_t)(r * AROW_U + seg * 4) * 4u, gp);
    }
#pragma unroll
    for (int it = 0; it < 4; it++) {
        int idx = tid + it * 256;
        int r = idx >> 3, seg = idx & 7;
        const float* gp = Bv + (size_t)(bn * 128 + r) * DIMK + k0 + seg * 4;
        cp_async16(b_base + (uint32_t)(r * BROW_F + seg * 4) * 4u, gp);
    }
    cp_commit();
}

__global__ __launch_bounds__(256, 2) void gemm_bf16(const float* __restrict__ Bv, int Brows) {
    extern __shared__ uint32_t sm[];
    const int bm = blockIdx.x, bn = blockIdx.y;
    const int tid = threadIdx.x, lane = tid & 31, warp = tid >> 5;
    const int wm = warp >> 2, wn = warp & 3;      // 2 x 4 warp grid, warp tile 64x32
    const int g = lane >> 2, tg = lane & 3;

    uint32_t smb;
    asm("{ .reg .u64 t; cvta.to.shared.u64 t, %1; cvt.u32.u64 %0, t; }" : "=r"(smb) : "l"(sm));

    // per-lane ldmatrix base offset within the A stage:
    // row = wm*64 + (lane%16), 16B-col = lane/16
    const uint32_t a_lm_off = (uint32_t)((wm * 64 + (lane & 15)) * AROW_U * 4 + (lane >> 4) * 16);

    float acc[4][4][4];
#pragma unroll
    for (int i = 0; i < 4; i++)
#pragma unroll
        for (int j = 0; j < 4; j++)
#pragma unroll
            for (int r = 0; r < 4; r++) acc[i][j][r] = 0.f;

    gemm_load_stage(smb, 0, bm, bn, 0, Bv, tid);
    gemm_load_stage(smb, 1, bm, bn, 32, Bv, tid);

    for (int kt = 0; kt < NKSTEP; kt++) {
        if (kt >= NKSTEP - 2) cp_wait0(); else cp_wait1();
        __syncthreads();

        const uint32_t a_stage = smb + (uint32_t)(kt % 3) * (STAGE_U * 4);
        const float*   Bs = (const float*)(sm + (kt % 3) * STAGE_U + A_STAGE_U);

#pragma unroll
        for (int ks = 0; ks < 2; ks++) {
            uint32_t af[4][4];
#pragma unroll
            for (int i = 0; i < 4; i++)
                ldmatrix_x4(af[i], a_stage + a_lm_off + (uint32_t)(i * 16 * AROW_U * 4 + ks * 32));

            const int kbB = ks * 16;
#pragma unroll
            for (int j = 0; j < 4; j++) {
                const int n0 = wn * 32 + j * 8 + g;
                float2 p0 = *(const float2*)(Bs + n0 * BROW_F + kbB + 2 * tg);
                float2 p1 = *(const float2*)(Bs + n0 * BROW_F + kbB + 2 * tg + 8);
                uint32_t bf[2];
                bf[0] = cvt_bf16x2(p0.x, p0.y);
                bf[1] = cvt_bf16x2(p1.x, p1.y);
#pragma unroll
                for (int i = 0; i < 4; i++) mma_bf16(acc[i][j], af[i], bf);
            }
        }

        if (kt + 2 < NKSTEP)
            gemm_load_stage(smb, (kt + 2) % 3, bm, bn, (kt + 2) * 32, Bv, tid);
    }

    // epilogue: c0,c1 = (row g, cols 2tg,2tg+1); c2,c3 = row g+8
#pragma unroll
    for (int i = 0; i < 4; i++) {
#pragma unroll
        for (int j = 0; j < 4; j++) {
            int row = bm * 128 + wm * 64 + i * 16 + g;
            int col = bn * 128 + wn * 32 + j * 8 + 2 * tg;
            if (row < Brows)
                *(float2*)(g_logits + (size_t)row * NTOT + col) =
                    make_float2(acc[i][j][0], acc[i][j][1]);
            if (row + 8 < Brows)
                *(float2*)(g_logits + (size_t)(row + 8) * NTOT + col) =
                    make_float2(acc[i][j][2], acc[i][j][3]);
        }
    }
}

// ---------------- kernel 3: per-row losses (R6 known-good version) ----------------
__global__ __launch_bounds__(256) void rowloss_kernel(const int* __restrict__ labels,
                                                      const int* __restrict__ cams) {
    extern __shared__ float srow[];        // NTOT floats (64 KB)
    __shared__ float scr[8];
    __shared__ float s_ori[CCAM];
    __shared__ unsigned hist[256];
    __shared__ unsigned sh_prefix;
    __shared__ int sh_need;

    const int b = blockIdx.x, tid = threadIdx.x;
    const int cam = cams[b], label = labels[b];
    const float invT = 1.0f / TEMP;
    const float* row = g_logits + (size_t)b * NTOT;

    for (int i = tid; i < NTOT; i += 256) srow[i] = row[i];
    __syncthreads();

    // intra-camera CE on own bank (unmasked)
    float mx = -1e30f;
    for (int i = tid; i < PBANK; i += 256) mx = fmaxf(mx, srow[cam * PBANK + i]);
    mx = block_max(mx, scr);
    float se = 0.f;
    for (int i = tid; i < PBANK; i += 256) se += expf((srow[cam * PBANK + i] - mx) * invT);
    se = block_sum(se, scr);
    const float ce = mx * invT + logf(se) - srow[cam * PBANK + label] * invT;

    // save positives, then mask them
    if (tid < CCAM) s_ori[tid] = srow[tid * PBANK + label];
    __syncthreads();
    if (tid < CCAM) srow[tid * PBANK + label] = -10000.0f;
    __syncthreads();

    // masked-row max + positives -> global stabilizer
    float m2 = -1e30f;
    for (int i = tid; i < NTOT; i += 256) m2 = fmaxf(m2, srow[i]);
    m2 = block_max(m2, scr);
    float M = m2;
#pragma unroll
    for (int c = 0; c < CCAM; c++) M = fmaxf(M, s_ori[c]);

    // exact top-K threshold via 4-pass 256-bin radix select
    unsigned prefix = 0;
    int need = KSEL;
    for (int p = 0; p < 4; p++) {
        const int shift = 24 - 8 * p;
        hist[tid] = 0u;
        __syncthreads();
        for (int i = tid; i < NTOT; i += 256) {
            unsigned key = fkey(srow[i]);
            bool ok = (p == 0) || ((key >> (shift + 8)) == (prefix >> (shift + 8)));
            unsigned bal = __ballot_sync(0xffffffffu, ok);
            if (ok) {
                unsigned bin = (key >> shift) & 0xFFu;
                unsigned mm = __match_any_sync(bal, bin);
                if ((int)(tid & 31) == __ffs(mm) - 1)
                    atomicAdd(&hist[bin], (unsigned)__popc(mm));
            }
        }
        __syncthreads();
        if (tid == 0) {
            int cum = 0, bsel = 0;
            for (int bb = 255; bb >= 0; --bb) {
                int h = (int)hist[bb];
                if (cum + h >= need) { bsel = bb; break; }
                cum += h;
            }
            sh_need = need - cum;
            sh_prefix = prefix | ((unsigned)bsel << shift);
        }
        __syncthreads();
        prefix = sh_prefix;
        need = sh_need;
        __syncthreads();
    }
    const float tval = funkey(prefix);

    // sum exp over top-K negatives (strict-greater + `need` copies of threshold)
    float local = 0.f;
    for (int i = tid; i < NTOT; i += 256) {
        float v = srow[i];
        if (fkey(v) > prefix) local += expf((v - M) * invT);
    }
    local = block_sum(local, scr);

    if (tid == 0) {
        float ssel = local + (float)need * expf((tval - M) * invT);
        float sori = 0.f, osum = 0.f;
#pragma unroll
        for (int c = 0; c < CCAM; c++) {
            sori += expf((s_ori[c] - M) * invT);
            osum += s_ori[c];
        }
        float lse = M * invT + logf(ssel + sori);
        g_lk[b] = lse - osum * invT * (1.0f / (float)CCAM);
        g_ce[b] = ce;
    }
}

// ---------------- kernel 4: per-camera means, warp-per-camera, deterministic ----------------
__global__ __launch_bounds__(256) void final_kernel(const int* __restrict__ cams,
                                                    float* __restrict__ out, int B) {
    __shared__ float s_i[CCAM], s_n[CCAM];
    const int w = threadIdx.x >> 5;
    const int l = threadIdx.x & 31;
    float se = 0.f, sl = 0.f, cn = 0.f;
    for (int b = l; b < B; b += 32) {
        if (cams[b] == w) { se += g_ce[b]; sl += g_lk[b]; cn += 1.f; }
    }
    se = warp_sum(se);
    sl = warp_sum(sl);
    cn = warp_sum(cn);
    if (l == 0) {
        s_i[w] = (cn > 0.f) ? se / cn : 0.f;
        s_n[w] = (cn > 0.f) ? sl / cn : 0.f;
    }
    __syncthreads();
    if (threadIdx.x == 0) {
        float a = 0.f, bsum = 0.f;
#pragma unroll
        for (int k = 0; k < CCAM; k++) { a += s_i[k]; bsum += s_n[k]; }
        out[0] = a;           // loss_intra
        out[1] = 0.5f * bsum; // loss_inter (LOSS_WEIGHT = 0.5)
    }
}

// ---------------- launch ----------------
extern "C" void kernel_launch(void* const* d_in, const int* in_sizes, int n_in,
                              void* d_out, int out_size) {
    const float* inputs = (const float*)d_in[0];
    const int*   labels = (const int*)d_in[1];
    const int*   cams   = (const int*)d_in[2];
    const float* tempV  = (const float*)d_in[3];
    const int B = in_sizes[1];  // labels element count

    prep_kernel<<<B, 256>>>(inputs);

    cudaFuncSetAttribute(gemm_bf16, cudaFuncAttributeMaxDynamicSharedMemorySize, GSMEM);
    dim3 grid((B + 127) / 128, NTOT / 128);   // bm fastest -> B-tile shared via L2
    gemm_bf16<<<grid, 256, GSMEM>>>(tempV, B);

    cudaFuncSetAttribute(rowloss_kernel, cudaFuncAttributeMaxDynamicSharedMemorySize,
                         NTOT * (int)sizeof(float));
    rowloss_kernel<<<B, 256, NTOT * sizeof(float)>>>(labels, cams);

    final_kernel<<<1, 256>>>(cams, (float*)d_out, B);
}